// round 1
// baseline (speedup 1.0000x reference)
#include <cuda_runtime.h>

// Problem constants
#define Bv 32
#define Av 1024
#define NNv 5
#define F_INv 128
#define E0v 128
#define E1v 32
#define Hv 32
#define NOUTv 32
#define NACTv 8
#define ROWS (Bv * Av)            // 32768 (b,j) rows

// scratch for hidden h = relu(relu(x@We0+be0)@We1+be1), [ROWS, 32]
__device__ float g_h[ROWS * E1v];

// ---------------------------------------------------------------------------
// Kernel 1: embedding MLP.  Block = 128 threads handles 32 rows.
// ---------------------------------------------------------------------------
__global__ __launch_bounds__(128) void mlp_kernel(
    const float* __restrict__ x,
    const float* __restrict__ We0, const float* __restrict__ be0,
    const float* __restrict__ We1, const float* __restrict__ be1)
{
    __shared__ float xs[32 * 128];   // 32 rows of x
    __shared__ float h1s[32 * 128];  // relu(x@We0+be0)

    const int tid = threadIdx.x;
    const int row0 = blockIdx.x * 32;

    // load 32 x-rows (coalesced; rows are contiguous)
    const float* xsrc = x + (size_t)row0 * F_INv;
    #pragma unroll
    for (int i = tid; i < 32 * 128; i += 128) xs[i] = xsrc[i];
    __syncthreads();

    // layer 0: thread t computes feature t for all 32 rows
    float acc[32];
    {
        const float bv = be0[tid];
        #pragma unroll
        for (int r = 0; r < 32; r++) acc[r] = bv;
        #pragma unroll 4
        for (int k = 0; k < 128; k++) {
            const float w = We0[k * 128 + tid];
            #pragma unroll
            for (int r = 0; r < 32; r++)
                acc[r] = fmaf(xs[r * 128 + k], w, acc[r]);
        }
        #pragma unroll
        for (int r = 0; r < 32; r++)
            h1s[r * 128 + tid] = fmaxf(acc[r], 0.0f);
    }
    __syncthreads();

    // layer 1: thread t -> output feature d = t&31, rows rg*8 .. rg*8+7
    {
        const int d = tid & 31;
        const int rg = tid >> 5;
        float acc2[8];
        const float bv = be1[d];
        #pragma unroll
        for (int r = 0; r < 8; r++) acc2[r] = bv;
        #pragma unroll 4
        for (int e = 0; e < 128; e++) {
            const float w = We1[e * 32 + d];
            #pragma unroll
            for (int r = 0; r < 8; r++)
                acc2[r] = fmaf(h1s[(rg * 8 + r) * 128 + e], w, acc2[r]);
        }
        #pragma unroll
        for (int r = 0; r < 8; r++) {
            const int row = row0 + rg * 8 + r;
            g_h[row * 32 + d] = fmaxf(acc2[r], 0.0f);
        }
    }
}

// ---------------------------------------------------------------------------
// Kernel 2: y row-sums + attention + output head.  One warp per (b,j) row.
// ---------------------------------------------------------------------------
__device__ __forceinline__ float warpsum(float v) {
    v += __shfl_xor_sync(0xffffffffu, v, 16);
    v += __shfl_xor_sync(0xffffffffu, v, 8);
    v += __shfl_xor_sync(0xffffffffu, v, 4);
    v += __shfl_xor_sync(0xffffffffu, v, 2);
    v += __shfl_xor_sync(0xffffffffu, v, 1);
    return v;
}

__global__ __launch_bounds__(256) void attn_kernel(
    const float* __restrict__ y,
    const float* __restrict__ W1, const float* __restrict__ b1,
    const float* __restrict__ W2, const float* __restrict__ b2,
    const float* __restrict__ W3, const float* __restrict__ b3,
    const float* __restrict__ W4, const float* __restrict__ b4,
    const float* __restrict__ Wp, const float* __restrict__ bp,
    float* __restrict__ out)
{
    const int lane = threadIdx.x & 31;
    const int warp = threadIdx.x >> 5;
    const int row = blockIdx.x * 8 + warp;   // < 32768

    // ---- ys[n] = sum_m y[row, n, m],  1024 floats each, float4 coalesced ----
    const float4* yp = (const float4*)(y + (size_t)row * (NNv * Av));
    float ys[NNv];
    #pragma unroll
    for (int n = 0; n < NNv; n++) {
        const float4* p = yp + n * 256;
        float s = 0.0f;
        #pragma unroll
        for (int i = 0; i < 8; i++) {
            float4 v = p[lane + i * 32];
            s += (v.x + v.y) + (v.z + v.w);
        }
        ys[n] = warpsum(s);   // all lanes hold the sum
    }

    // ---- per-row attention math; lane d handles hidden dim d ----
    const float hd  = g_h[row * 32 + lane];
    const float b1v = b1[lane], b2v = b2[lane], b3v = b3[lane], b4v = b4[lane];

    float g1 = b1v, g2 = 0.0f, g3 = 0.0f;
    #pragma unroll
    for (int e = 0; e < 32; e++) {
        const float he = __shfl_sync(0xffffffffu, hd, e);
        g1 = fmaf(he, W1[e * 32 + lane], g1);
        g2 = fmaf(he, W2[e * 32 + lane], g2);
        g3 = fmaf(he, W3[e * 32 + lane], g3);
    }
    g1 = fmaxf(g1, 0.0f);

    // scores_n = dot(g1, relu(ys_n*g2 + b2))
    float sc[NNv];
    #pragma unroll
    for (int n = 0; n < NNv; n++) {
        float t = g1 * fmaxf(fmaf(ys[n], g2, b2v), 0.0f);
        sc[n] = warpsum(t);
    }

    // softmax over 5 (redundant in every lane — scalar work)
    float m = sc[0];
    #pragma unroll
    for (int n = 1; n < NNv; n++) m = fmaxf(m, sc[n]);
    float att[NNv], denom = 0.0f;
    #pragma unroll
    for (int n = 0; n < NNv; n++) { att[n] = expf(sc[n] - m); denom += att[n]; }
    const float inv = 1.0f / denom;
    float s = 0.0f;
    #pragma unroll
    for (int n = 0; n < NNv; n++) { att[n] *= inv; s = fmaf(att[n], ys[n], s); }

    // ctx = s*g3 + b3  (since sum att = 1)
    const float ctx = fmaf(s, g3, b3v);

    // out = ctx @ W4 + b4
    float od = b4v;
    #pragma unroll
    for (int e = 0; e < 32; e++) {
        const float ce = __shfl_sync(0xffffffffu, ctx, e);
        od = fmaf(ce, W4[e * 32 + lane], od);
    }

    // logits = out @ Wp + bp  (lanes 0..7)
    float la = (lane < NACTv) ? bp[lane] : 0.0f;
    #pragma unroll
    for (int e = 0; e < 32; e++) {
        const float oe = __shfl_sync(0xffffffffu, od, e);
        const float wv = (lane < NACTv) ? Wp[e * NACTv + lane] : 0.0f;
        la = fmaf(oe, wv, la);
    }

    // ---- writes: [logits (ROWS*8) | att (ROWS*5)] ----
    if (lane < NACTv)
        out[(size_t)row * NACTv + lane] = la;
    float av = 0.0f;
    #pragma unroll
    for (int n = 0; n < NNv; n++) if (lane == n) av = att[n];
    if (lane < NNv)
        out[(size_t)ROWS * NACTv + (size_t)row * NNv + lane] = av;
}

// ---------------------------------------------------------------------------
extern "C" void kernel_launch(void* const* d_in, const int* in_sizes, int n_in,
                              void* d_out, int out_size)
{
    const float* x   = (const float*)d_in[0];
    const float* y   = (const float*)d_in[1];
    const float* We0 = (const float*)d_in[2];
    const float* be0 = (const float*)d_in[3];
    const float* We1 = (const float*)d_in[4];
    const float* be1 = (const float*)d_in[5];
    const float* W1  = (const float*)d_in[6];
    const float* b1  = (const float*)d_in[7];
    const float* W2  = (const float*)d_in[8];
    const float* b2  = (const float*)d_in[9];
    const float* W3  = (const float*)d_in[10];
    const float* b3  = (const float*)d_in[11];
    const float* W4  = (const float*)d_in[12];
    const float* b4  = (const float*)d_in[13];
    const float* Wp  = (const float*)d_in[14];
    const float* bp  = (const float*)d_in[15];
    float* out = (float*)d_out;

    mlp_kernel<<<ROWS / 32, 128>>>(x, We0, be0, We1, be1);
    attn_kernel<<<ROWS / 8, 256>>>(y, W1, b1, W2, b2, W3, b3, W4, b4, Wp, bp, out);
}

// round 2
// speedup vs baseline: 1.5158x; 1.5158x over previous
#include <cuda_runtime.h>

// Problem constants
#define Bv 32
#define Av 1024
#define NNv 5
#define F_INv 128
#define E0v 128
#define E1v 32
#define NACTv 8
#define ROWS (Bv * Av)            // 32768
#define CHUNKS (ROWS / 4)         // 8192 chunks of 4 rows

#define NTHREADS 512
#define NWARPS 16
#define GRID 152

// dynamic smem layout, offsets in floats
#define OFF_WE0 0          // 128*128
#define OFF_WE1 16384      // 128*32
#define OFF_W1  20480      // 32*32
#define OFF_W2  21504
#define OFF_W3  22528
#define OFF_W4  23552
#define OFF_WP  24576      // 32*8
#define OFF_BE0 24832      // 128
#define OFF_BE1 24960      // 32
#define OFF_B1  24992
#define OFF_B2  25024
#define OFF_B3  25056
#define OFF_B4  25088
#define OFF_BP  25120      // 8
#define OFF_XBUF 25216     // 16 warps * 512 floats (4 rows x 128), 16B aligned
#define SMEM_FLOATS 33408
#define SMEM_BYTES (SMEM_FLOATS * 4)

__device__ unsigned int g_ctr;

__device__ __forceinline__ float warpsum(float v) {
    v += __shfl_xor_sync(0xffffffffu, v, 16);
    v += __shfl_xor_sync(0xffffffffu, v, 8);
    v += __shfl_xor_sync(0xffffffffu, v, 4);
    v += __shfl_xor_sync(0xffffffffu, v, 2);
    v += __shfl_xor_sync(0xffffffffu, v, 1);
    return v;
}

__device__ __forceinline__ void fma4(float4& a, float s, const float4& w) {
    a.x = fmaf(s, w.x, a.x);
    a.y = fmaf(s, w.y, a.y);
    a.z = fmaf(s, w.z, a.z);
    a.w = fmaf(s, w.w, a.w);
}

__global__ __launch_bounds__(NTHREADS, 1) void fused_kernel(
    const float* __restrict__ x,
    const float* __restrict__ y,
    const float* __restrict__ We0, const float* __restrict__ be0,
    const float* __restrict__ We1, const float* __restrict__ be1,
    const float* __restrict__ W1, const float* __restrict__ b1,
    const float* __restrict__ W2, const float* __restrict__ b2,
    const float* __restrict__ W3, const float* __restrict__ b3,
    const float* __restrict__ W4, const float* __restrict__ b4,
    const float* __restrict__ Wp, const float* __restrict__ bp,
    float* __restrict__ out)
{
    extern __shared__ float sm[];
    const int tid  = threadIdx.x;
    const int lane = tid & 31;
    const int w    = tid >> 5;

    // ---- cooperative weight load into smem ----
    for (int i = tid; i < 16384; i += NTHREADS) sm[OFF_WE0 + i] = We0[i];
    for (int i = tid; i < 4096;  i += NTHREADS) sm[OFF_WE1 + i] = We1[i];
    for (int i = tid; i < 1024;  i += NTHREADS) {
        sm[OFF_W1 + i] = W1[i];
        sm[OFF_W2 + i] = W2[i];
        sm[OFF_W3 + i] = W3[i];
        sm[OFF_W4 + i] = W4[i];
    }
    if (tid < 256) sm[OFF_WP + tid] = Wp[tid];
    if (tid < 128) { sm[OFF_BE0 + tid] = be0[tid]; }
    if (tid < 32) {
        sm[OFF_BE1 + tid] = be1[tid];
        sm[OFF_B1 + tid] = b1[tid];
        sm[OFF_B2 + tid] = b2[tid];
        sm[OFF_B3 + tid] = b3[tid];
        sm[OFF_B4 + tid] = b4[tid];
        if (tid < 8) sm[OFF_BP + tid] = bp[tid];
    }
    __syncthreads();

    const float4* We0s4 = (const float4*)(sm + OFF_WE0);
    const float4* be0s4 = (const float4*)(sm + OFF_BE0);
    float4* xb4 = (float4*)(sm + OFF_XBUF) + w * 128;   // 4 rows x 32 float4

    const float b1v = sm[OFF_B1 + lane];
    const float b2v = sm[OFF_B2 + lane];
    const float b3v = sm[OFF_B3 + lane];
    const float b4v = sm[OFF_B4 + lane];
    const float be1v = sm[OFF_BE1 + lane];
    const float bpv = (lane < NACTv) ? sm[OFF_BP + lane] : 0.0f;

    // ---- warp-level work stealing over 4-row chunks ----
    for (;;) {
        unsigned int c;
        if (lane == 0) c = atomicAdd(&g_ctr, 1u);
        c = __shfl_sync(0xffffffffu, c, 0);
        if (c >= CHUNKS) break;
        const int row0 = (int)c * 4;

        // ---- stage x (4 rows) into per-warp smem ----
        #pragma unroll
        for (int r = 0; r < 4; r++)
            xb4[r * 32 + lane] = ((const float4*)(x + (size_t)(row0 + r) * F_INv))[lane];
        __syncwarp();

        // ---- layer 0: 4 rows, lane owns features lane*4..lane*4+3 ----
        float4 acc0 = be0s4[lane], acc1 = acc0, acc2 = acc0, acc3 = acc0;
        #pragma unroll 8
        for (int k4 = 0; k4 < 32; k4++) {
            float4 w0 = We0s4[(k4 * 4 + 0) * 32 + lane];
            float4 w1 = We0s4[(k4 * 4 + 1) * 32 + lane];
            float4 w2 = We0s4[(k4 * 4 + 2) * 32 + lane];
            float4 w3 = We0s4[(k4 * 4 + 3) * 32 + lane];
            float4 xk;
            xk = xb4[0 * 32 + k4];
            fma4(acc0, xk.x, w0); fma4(acc0, xk.y, w1); fma4(acc0, xk.z, w2); fma4(acc0, xk.w, w3);
            xk = xb4[1 * 32 + k4];
            fma4(acc1, xk.x, w0); fma4(acc1, xk.y, w1); fma4(acc1, xk.z, w2); fma4(acc1, xk.w, w3);
            xk = xb4[2 * 32 + k4];
            fma4(acc2, xk.x, w0); fma4(acc2, xk.y, w1); fma4(acc2, xk.z, w2); fma4(acc2, xk.w, w3);
            xk = xb4[3 * 32 + k4];
            fma4(acc3, xk.x, w0); fma4(acc3, xk.y, w1); fma4(acc3, xk.z, w2); fma4(acc3, xk.w, w3);
        }
        __syncwarp();
        // relu + overwrite xbuf with h1
        acc0.x = fmaxf(acc0.x, 0.f); acc0.y = fmaxf(acc0.y, 0.f); acc0.z = fmaxf(acc0.z, 0.f); acc0.w = fmaxf(acc0.w, 0.f);
        acc1.x = fmaxf(acc1.x, 0.f); acc1.y = fmaxf(acc1.y, 0.f); acc1.z = fmaxf(acc1.z, 0.f); acc1.w = fmaxf(acc1.w, 0.f);
        acc2.x = fmaxf(acc2.x, 0.f); acc2.y = fmaxf(acc2.y, 0.f); acc2.z = fmaxf(acc2.z, 0.f); acc2.w = fmaxf(acc2.w, 0.f);
        acc3.x = fmaxf(acc3.x, 0.f); acc3.y = fmaxf(acc3.y, 0.f); acc3.z = fmaxf(acc3.z, 0.f); acc3.w = fmaxf(acc3.w, 0.f);
        xb4[0 * 32 + lane] = acc0;
        xb4[1 * 32 + lane] = acc1;
        xb4[2 * 32 + lane] = acc2;
        xb4[3 * 32 + lane] = acc3;
        __syncwarp();

        // ---- layer 1: lane owns output dim `lane` ----
        float a1_0 = be1v, a1_1 = be1v, a1_2 = be1v, a1_3 = be1v;
        #pragma unroll 8
        for (int k4 = 0; k4 < 32; k4++) {
            float w0 = sm[OFF_WE1 + (k4 * 4 + 0) * 32 + lane];
            float w1 = sm[OFF_WE1 + (k4 * 4 + 1) * 32 + lane];
            float w2 = sm[OFF_WE1 + (k4 * 4 + 2) * 32 + lane];
            float w3 = sm[OFF_WE1 + (k4 * 4 + 3) * 32 + lane];
            float4 hk;
            hk = xb4[0 * 32 + k4];
            a1_0 = fmaf(hk.x, w0, a1_0); a1_0 = fmaf(hk.y, w1, a1_0); a1_0 = fmaf(hk.z, w2, a1_0); a1_0 = fmaf(hk.w, w3, a1_0);
            hk = xb4[1 * 32 + k4];
            a1_1 = fmaf(hk.x, w0, a1_1); a1_1 = fmaf(hk.y, w1, a1_1); a1_1 = fmaf(hk.z, w2, a1_1); a1_1 = fmaf(hk.w, w3, a1_1);
            hk = xb4[2 * 32 + k4];
            a1_2 = fmaf(hk.x, w0, a1_2); a1_2 = fmaf(hk.y, w1, a1_2); a1_2 = fmaf(hk.z, w2, a1_2); a1_2 = fmaf(hk.w, w3, a1_2);
            hk = xb4[3 * 32 + k4];
            a1_3 = fmaf(hk.x, w0, a1_3); a1_3 = fmaf(hk.y, w1, a1_3); a1_3 = fmaf(hk.z, w2, a1_3); a1_3 = fmaf(hk.w, w3, a1_3);
        }
        float h[4];
        h[0] = fmaxf(a1_0, 0.f); h[1] = fmaxf(a1_1, 0.f);
        h[2] = fmaxf(a1_2, 0.f); h[3] = fmaxf(a1_3, 0.f);

        // ---- g1/g2/g3 = h@W1..W3 for all 4 rows (weights shared) ----
        float g1[4], g2[4], g3[4];
        #pragma unroll
        for (int r = 0; r < 4; r++) { g1[r] = b1v; g2[r] = 0.f; g3[r] = 0.f; }
        #pragma unroll 8
        for (int e = 0; e < 32; e++) {
            const float w1e = sm[OFF_W1 + e * 32 + lane];
            const float w2e = sm[OFF_W2 + e * 32 + lane];
            const float w3e = sm[OFF_W3 + e * 32 + lane];
            #pragma unroll
            for (int r = 0; r < 4; r++) {
                const float he = __shfl_sync(0xffffffffu, h[r], e);
                g1[r] = fmaf(he, w1e, g1[r]);
                g2[r] = fmaf(he, w2e, g2[r]);
                g3[r] = fmaf(he, w3e, g3[r]);
            }
        }
        #pragma unroll
        for (int r = 0; r < 4; r++) g1[r] = fmaxf(g1[r], 0.f);

        // ---- per-row: y reduction + attention epilogue ----
        #pragma unroll 1
        for (int r = 0; r < 4; r++) {
            const int row = row0 + r;
            const float4* yp = (const float4*)(y + (size_t)row * (NNv * Av));
            float ys[NNv];
            #pragma unroll
            for (int n = 0; n < NNv; n++) {
                const float4* p = yp + n * 256;
                float s = 0.0f;
                #pragma unroll
                for (int i = 0; i < 8; i++) {
                    float4 v = p[lane + i * 32];
                    s += (v.x + v.y) + (v.z + v.w);
                }
                ys[n] = warpsum(s);
            }

            float sc[NNv];
            #pragma unroll
            for (int n = 0; n < NNv; n++) {
                float t = g1[r] * fmaxf(fmaf(ys[n], g2[r], b2v), 0.0f);
                sc[n] = warpsum(t);
            }

            float m = sc[0];
            #pragma unroll
            for (int n = 1; n < NNv; n++) m = fmaxf(m, sc[n]);
            float att[NNv], denom = 0.0f;
            #pragma unroll
            for (int n = 0; n < NNv; n++) { att[n] = __expf(sc[n] - m); denom += att[n]; }
            const float inv = 1.0f / denom;
            float s = 0.0f;
            #pragma unroll
            for (int n = 0; n < NNv; n++) { att[n] *= inv; s = fmaf(att[n], ys[n], s); }

            const float ctx = fmaf(s, g3[r], b3v);

            float od = b4v;
            #pragma unroll 8
            for (int e = 0; e < 32; e++) {
                const float ce = __shfl_sync(0xffffffffu, ctx, e);
                od = fmaf(ce, sm[OFF_W4 + e * 32 + lane], od);
            }

            float la = bpv;
            #pragma unroll 8
            for (int e = 0; e < 32; e++) {
                const float oe = __shfl_sync(0xffffffffu, od, e);
                la = fmaf(oe, sm[OFF_WP + e * NACTv + (lane & 7)], la);
            }

            if (lane < NACTv)
                out[(size_t)row * NACTv + lane] = la;
            float av = 0.0f;
            #pragma unroll
            for (int n = 0; n < NNv; n++) if (lane == n) av = att[n];
            if (lane < NNv)
                out[(size_t)ROWS * NACTv + (size_t)row * NNv + lane] = av;
        }
    }
}

// ---------------------------------------------------------------------------
extern "C" void kernel_launch(void* const* d_in, const int* in_sizes, int n_in,
                              void* d_out, int out_size)
{
    const float* x   = (const float*)d_in[0];
    const float* y   = (const float*)d_in[1];
    const float* We0 = (const float*)d_in[2];
    const float* be0 = (const float*)d_in[3];
    const float* We1 = (const float*)d_in[4];
    const float* be1 = (const float*)d_in[5];
    const float* W1  = (const float*)d_in[6];
    const float* b1  = (const float*)d_in[7];
    const float* W2  = (const float*)d_in[8];
    const float* b2  = (const float*)d_in[9];
    const float* W3  = (const float*)d_in[10];
    const float* b3  = (const float*)d_in[11];
    const float* W4  = (const float*)d_in[12];
    const float* b4  = (const float*)d_in[13];
    const float* Wp  = (const float*)d_in[14];
    const float* bp  = (const float*)d_in[15];
    float* out = (float*)d_out;

    static int configured = 0;
    cudaFuncSetAttribute(fused_kernel, cudaFuncAttributeMaxDynamicSharedMemorySize, SMEM_BYTES);
    (void)configured;

    void* ctr_ptr = nullptr;
    cudaGetSymbolAddress(&ctr_ptr, g_ctr);
    cudaMemsetAsync(ctr_ptr, 0, sizeof(unsigned int));

    fused_kernel<<<GRID, NTHREADS, SMEM_BYTES>>>(
        x, y, We0, be0, We1, be1, W1, b1, W2, b2, W3, b3, W4, b4, Wp, bp, out);
}